// round 13
// baseline (speedup 1.0000x reference)
#include <cuda_runtime.h>
#include <cuda_fp16.h>
#include <math.h>
#include <stdint.h>

#define T_TOK 2048
#define NE 64
#define KTOP 8
#define SELK 4
#define HD 2048
#define FI 768
#define TWOF 1536
#define BM 64
#define MAXMT 320            // sum ceil(cnt/64) <= 16384/64 + 64
#define CAP 20480            // 16384 + 64*64 padded rows

// ---------------- scratch (device globals; no runtime allocation) ----------------
__device__ float d_topv[T_TOK * KTOP];
__device__ int   d_topi[T_TOK * KTOP];
__device__ int   d_rer[T_TOK * KTOP];
__device__ int d_tile_e[MAXMT];
__device__ int d_tile_base[MAXMT];
__device__ int d_tile_lim[MAXMT];
__device__ int d_nmt;
__device__ int d_row_src[CAP];
__device__ float d_row_w[CAP];
__device__ int d_row_of[T_TOK * KTOP];
__device__ __align__(16) __half d_xh[(size_t)T_TOK * HD];          // fp16 tokens
__device__ __align__(16) __half d_guph[(size_t)NE * TWOF * HD];    // fp16 gate_up (402 MB)
__device__ __align__(16) __half d_dwnh[(size_t)NE * HD * FI];      // fp16 down (201 MB)
__device__ __align__(16) __half d_hacth[(size_t)CAP * FI];         // fp16 silu(g)*u
__device__ float d_y[(size_t)CAP * HD];

// ---------------- helpers (legacy mma.sync path; tcgen05 unavailable:
// harness ptxas target is sm_103 without the 'a' suffix) ----------------------
__device__ __forceinline__ uint32_t packh2(float lo, float hi) {
    uint32_t u;
    asm("cvt.rn.f16x2.f32 %0, %1, %2;" : "=r"(u) : "f"(hi), "f"(lo));
    return u;
}
__device__ __forceinline__ uint2 cvt4h(float4 v) {
    return make_uint2(packh2(v.x, v.y), packh2(v.z, v.w));
}
__device__ __forceinline__ void mma_f16(float* c, const uint32_t* a, uint32_t b0, uint32_t b1) {
    asm volatile(
        "mma.sync.aligned.m16n8k16.row.col.f32.f16.f16.f32 "
        "{%0,%1,%2,%3}, {%4,%5,%6,%7}, {%8,%9}, {%0,%1,%2,%3};\n"
        : "+f"(c[0]), "+f"(c[1]), "+f"(c[2]), "+f"(c[3])
        : "r"(a[0]), "r"(a[1]), "r"(a[2]), "r"(a[3]), "r"(b0), "r"(b1));
}
__device__ __forceinline__ void ldsm4(uint32_t* r, uint32_t a) {
    asm volatile("ldmatrix.sync.aligned.m8n8.x4.shared.b16 {%0,%1,%2,%3}, [%4];"
                 : "=r"(r[0]), "=r"(r[1]), "=r"(r[2]), "=r"(r[3]) : "r"(a));
}
__device__ __forceinline__ uint32_t smem_u32(const void* p) {
    uint32_t a;
    asm("{ .reg .u64 t; cvta.to.shared.u64 t, %1; cvt.u32.u64 %0, t; }" : "=r"(a) : "l"(p));
    return a;
}
__device__ __forceinline__ void cpa16(uint32_t dst, const void* src) {
    asm volatile("cp.async.cg.shared.global [%0], [%1], 16;" :: "r"(dst), "l"(src));
}
#define CP_COMMIT() asm volatile("cp.async.commit_group;" ::: "memory")
#define CP_WAIT1()  asm volatile("cp.async.wait_group 1;" ::: "memory")
#define CP_WAIT0()  asm volatile("cp.async.wait_group 0;" ::: "memory")

// ---------------- router: 4 tokens per block ----------------
__global__ __launch_bounds__(256) void router_kernel(const float* __restrict__ x,
                                                     const float* __restrict__ gw) {
    __shared__ float sx[4][HD];
    __shared__ float sl[4][NE];
    int t0 = blockIdx.x * 4;
    int tid = threadIdx.x;
    for (int i = tid; i < 4 * HD; i += 256)
        ((float*)sx)[i] = x[(size_t)t0 * HD + i];
    __syncthreads();

    int e   = tid >> 2;
    int sub = tid & 3;
    const float4* wp = (const float4*)(gw + (size_t)e * HD + sub * (HD / 4));
    float s0 = 0.f, s1 = 0.f, s2 = 0.f, s3 = 0.f;
    const float4* xp0 = (const float4*)(sx[0] + sub * (HD / 4));
    const float4* xp1 = (const float4*)(sx[1] + sub * (HD / 4));
    const float4* xp2 = (const float4*)(sx[2] + sub * (HD / 4));
    const float4* xp3 = (const float4*)(sx[3] + sub * (HD / 4));
#pragma unroll 4
    for (int i = 0; i < HD / 16; i++) {
        float4 w = wp[i];
        float4 a0 = xp0[i], a1 = xp1[i], a2 = xp2[i], a3 = xp3[i];
        s0 += a0.x * w.x + a0.y * w.y + a0.z * w.z + a0.w * w.w;
        s1 += a1.x * w.x + a1.y * w.y + a1.z * w.z + a1.w * w.w;
        s2 += a2.x * w.x + a2.y * w.y + a2.z * w.z + a2.w * w.w;
        s3 += a3.x * w.x + a3.y * w.y + a3.z * w.z + a3.w * w.w;
    }
    s0 += __shfl_xor_sync(0xffffffffu, s0, 1); s0 += __shfl_xor_sync(0xffffffffu, s0, 2);
    s1 += __shfl_xor_sync(0xffffffffu, s1, 1); s1 += __shfl_xor_sync(0xffffffffu, s1, 2);
    s2 += __shfl_xor_sync(0xffffffffu, s2, 1); s2 += __shfl_xor_sync(0xffffffffu, s2, 2);
    s3 += __shfl_xor_sync(0xffffffffu, s3, 1); s3 += __shfl_xor_sync(0xffffffffu, s3, 2);
    if (sub == 0) { sl[0][e] = s0; sl[1][e] = s1; sl[2][e] = s2; sl[3][e] = s3; }
    __syncthreads();

    int wrp = tid >> 5;
    if (wrp < 4) {
        int lane = tid & 31;
        int t = t0 + wrp;
        float v0 = sl[wrp][lane], v1 = sl[wrp][lane + 32];
        float m = fmaxf(v0, v1);
        for (int off = 16; off; off >>= 1) m = fmaxf(m, __shfl_xor_sync(0xffffffffu, m, off));
        float e0 = expf(v0 - m), e1 = expf(v1 - m);
        float ss = e0 + e1;
        for (int off = 16; off; off >>= 1) ss += __shfl_xor_sync(0xffffffffu, ss, off);
        float p0 = e0 / ss, p1 = e1 / ss;

        float tv[KTOP]; int ti[KTOP];
#pragma unroll
        for (int k = 0; k < KTOP; k++) {
            float b; int bi;
            if (p0 >= p1) { b = p0; bi = lane; } else { b = p1; bi = lane + 32; }
            for (int off = 16; off; off >>= 1) {
                float ob = __shfl_xor_sync(0xffffffffu, b, off);
                int obi  = __shfl_xor_sync(0xffffffffu, bi, off);
                if (ob > b || (ob == b && obi < bi)) { b = ob; bi = obi; }
            }
            tv[k] = b; ti[k] = bi;
            if (bi < 32) { if (lane == bi) p0 = -1.f; }
            else         { if (lane == bi - 32) p1 = -1.f; }
        }
        if (lane == 0) {
            float tsum = 0.f;
#pragma unroll
            for (int k = 0; k < KTOP; k++) tsum += tv[k];
            tsum = fmaxf(tsum, 1e-12f);
#pragma unroll
            for (int k = 0; k < KTOP; k++) {
                d_topv[t * KTOP + k] = tv[k] / tsum;
                d_topi[t * KTOP + k] = ti[k];
            }
        }
    }
}

// ---------------- one-shot fp32 -> fp16 conversion of gup, dwn, x ----------------
__global__ __launch_bounds__(256) void cvtwx_kernel(const float* __restrict__ gup,
                                                    const float* __restrict__ dwn,
                                                    const float* __restrict__ x) {
    const size_t NG = (size_t)NE * TWOF * HD / 8;   // 8-float chunks
    const size_t ND = (size_t)NE * HD * FI / 8;
    const size_t NX = (size_t)T_TOK * HD / 8;
    size_t i = (size_t)blockIdx.x * 256 + threadIdx.x;
    const float4* src; uint4* dst; size_t j;
    if (i < NG)            { src = (const float4*)gup; dst = (uint4*)d_guph; j = i; }
    else if (i < NG + ND)  { src = (const float4*)dwn; dst = (uint4*)d_dwnh; j = i - NG; }
    else if (i < NG + ND + NX) { src = (const float4*)x; dst = (uint4*)d_xh; j = i - NG - ND; }
    else return;
    float4 a = src[j * 2], b = src[j * 2 + 1];
    uint2 p = cvt4h(a), q = cvt4h(b);
    dst[j] = make_uint4(p.x, p.y, q.x, q.y);
}

// ---------------- routeplan: masks -> mapping -> reroute -> tiles -> scatter ----
__global__ __launch_bounds__(1024) void routeplan_kernel(const float* __restrict__ sim) {
    __shared__ unsigned pm[2], smk[2];
    __shared__ int cnts[NE], maps[NE], poff[NE], cur[NE];
    int tid = threadIdx.x;
    if (tid < 2) { pm[tid] = 0u; smk[tid] = 0u; }
    if (tid < NE) { cnts[tid] = 0; cur[tid] = 0; }
    __syncthreads();

    for (int a = tid; a < T_TOK * KTOP; a += 1024) {
        int e0 = d_topi[a];
        if ((a & 7) < SELK) atomicOr(&pm[e0 >> 5], 1u << (e0 & 31));
        else                atomicOr(&smk[e0 >> 5], 1u << (e0 & 31));
    }
    __syncthreads();

    if (tid < NE) {
        int e = tid;
        unsigned pm0 = pm[0], pm1 = pm[1];
        bool prim = (e < 32) ? ((pm0 >> e) & 1) : ((pm1 >> (e - 32)) & 1);
        bool sec  = (e < 32) ? ((smk[0] >> e) & 1) : ((smk[1] >> (e - 32)) & 1);
        int best = 0; float bs = -INFINITY;
        for (int p = 0; p < NE; p++) {
            bool pp = (p < 32) ? ((pm0 >> p) & 1) : ((pm1 >> (p - 32)) & 1);
            if (!pp) continue;
            float v = (p == e) ? 1.0f : sim[e * NE + p];
            if (v > bs) { bs = v; best = p; }
        }
        int mp = e;
        if (sec && !prim && bs >= 0.5f) mp = best;
        maps[e] = mp;
    }
    __syncthreads();

    for (int a = tid; a < T_TOK * KTOP; a += 1024) {
        int e0 = d_topi[a];
        int e = ((a & 7) < SELK) ? e0 : maps[e0];
        d_rer[a] = e;
        atomicAdd(&cnts[e], 1);
    }
    __syncthreads();

    if (tid == 0) {
        int off = 0, nt = 0;
        for (int e = 0; e < NE; e++) {
            poff[e] = off;
            int c = cnts[e];
            int mt = (c + BM - 1) / BM;
            for (int i = 0; i < mt; i++) {
                d_tile_e[nt] = e;
                d_tile_base[nt] = off + i * BM;
                int lm = c - i * BM; if (lm > BM) lm = BM;
                d_tile_lim[nt] = lm;
                nt++;
            }
            off += mt * BM;
        }
        d_nmt = nt;
    }
    __syncthreads();

    for (int a = tid; a < T_TOK * KTOP; a += 1024) {
        int e = d_rer[a];
        int pos = poff[e] + atomicAdd(&cur[e], 1);
        d_row_src[pos] = a >> 3;
        d_row_w[pos] = d_topv[a];
        d_row_of[a] = pos;
    }
}

// ======================================================================
// GEMM1 (fp16 mma.sync, all-cp.async operands) + fused SwiGLU -> fp16 hact.
// CTA: 64 rows x (64 gate + 64 up cols), 4 warps, BK=32 k-halves/stage.
// Per quad (4 lanes x 16B) = one contiguous 64B row-chunk (coalesced).
// ======================================================================
__global__ __launch_bounds__(128, 4) void gemm1_kernel() {
    int bx = blockIdx.x;
    if (bx >= d_nmt) return;
    int e = d_tile_e[bx], base = d_tile_base[bx], lim = d_tile_lim[bx];
    int n0 = blockIdx.y * 64;          // gate column base in [0, 768)

    __shared__ __align__(16) uint32_t As[2][64][20];    // 64 rows x 16 half2 (+pad)
    __shared__ __align__(16) uint32_t Bs[2][128][20];   // rows 0-63 gate, 64-127 up
    __shared__ int srow[64];

    int tid = threadIdx.x;
    // pad rows point at token 0: garbage values, outputs masked by lim
    if (tid < 64) srow[tid] = (tid < lim) ? d_row_src[base + tid] : 0;
    __syncthreads();

    int q = tid >> 2, lq = tid & 3;    // quad row, 16B chunk within 64B row-chunk
    const __half* aSrc0 = d_xh + (size_t)srow[q] * HD + lq * 8;
    const __half* aSrc1 = d_xh + (size_t)srow[q + 32] * HD + lq * 8;
    const __half* bSrc[4];
#pragma unroll
    for (int i = 0; i < 4; i++) {
        int row = q + i * 32;
        int br = (row < 64) ? (n0 + row) : (FI + n0 + (row - 64));
        bSrc[i] = d_guph + ((size_t)e * TWOF + br) * HD + lq * 8;
    }

    uint32_t asb[2] = { smem_u32(&As[0][0][0]), smem_u32(&As[1][0][0]) };
    uint32_t bsb[2] = { smem_u32(&Bs[0][0][0]), smem_u32(&Bs[1][0][0]) };
    uint32_t aOff0 = (q * 20 + lq * 4) * 4;
    uint32_t aOff1 = ((q + 32) * 20 + lq * 4) * 4;
    uint32_t bOff[4];
#pragma unroll
    for (int i = 0; i < 4; i++) bOff[i] = ((q + i * 32) * 20 + lq * 4) * 4;

    int warp = tid >> 5, lane = tid & 31;
    int wm = warp >> 1, wn = warp & 1;
    int g = lane >> 2, tg = lane & 3;
    int offA = ((lane & 7) + ((lane >> 3) & 1) * 8) * 20 + (lane >> 4) * 4;
    int offB = ((lane & 7) + ((lane >> 4) & 1) * 8) * 20 + ((lane >> 3) & 1) * 4;

    float cg[2][4][4] = {};
    float cu[2][4][4] = {};

    const int NIT = HD / 32;           // 64 stages
    // prologue: stage 0 into buffer 0
    cpa16(asb[0] + aOff0, aSrc0);
    cpa16(asb[0] + aOff1, aSrc1);
#pragma unroll
    for (int i = 0; i < 4; i++) cpa16(bsb[0] + bOff[i], bSrc[i]);
    CP_COMMIT();

    int buf = 0;
    for (int it = 0; it < NIT; it++) {
        if (it + 1 < NIT) {
            int ko = (it + 1) * 32;    // halves
            int d = buf ^ 1;
            cpa16(asb[d] + aOff0, aSrc0 + ko);
            cpa16(asb[d] + aOff1, aSrc1 + ko);
#pragma unroll
            for (int i = 0; i < 4; i++) cpa16(bsb[d] + bOff[i], bSrc[i] + ko);
            CP_COMMIT();
            CP_WAIT1();
        } else {
            CP_WAIT0();
        }
        __syncthreads();
#pragma unroll
        for (int kk = 0; kk < 16; kk += 8) {
            uint32_t af[2][4], bg[8], bu[8];
            ldsm4(af[0], asb[buf] + 4u * (offA + (wm * 32) * 20 + kk));
            ldsm4(af[1], asb[buf] + 4u * (offA + (wm * 32 + 16) * 20 + kk));
            ldsm4(bg + 0, bsb[buf] + 4u * (offB + (wn * 32) * 20 + kk));
            ldsm4(bg + 4, bsb[buf] + 4u * (offB + (wn * 32 + 16) * 20 + kk));
            ldsm4(bu + 0, bsb[buf] + 4u * (offB + (64 + wn * 32) * 20 + kk));
            ldsm4(bu + 4, bsb[buf] + 4u * (offB + (64 + wn * 32 + 16) * 20 + kk));
#pragma unroll
            for (int ni = 0; ni < 4; ni++) {
#pragma unroll
                for (int mi = 0; mi < 2; mi++) {
                    mma_f16(cg[mi][ni], af[mi], bg[ni * 2], bg[ni * 2 + 1]);
                    mma_f16(cu[mi][ni], af[mi], bu[ni * 2], bu[ni * 2 + 1]);
                }
            }
        }
        __syncthreads();               // protect buf before it's refilled
        buf ^= 1;
    }

    // fused SwiGLU epilogue -> fp16 hact
#pragma unroll
    for (int mi = 0; mi < 2; mi++) {
#pragma unroll
        for (int half = 0; half < 2; half++) {
            int row = wm * 32 + mi * 16 + g + half * 8;
            if (row < lim) {
                __half2* dst = (__half2*)(d_hacth + (size_t)(base + row) * FI + n0 + wn * 32);
#pragma unroll
                for (int ni = 0; ni < 4; ni++) {
                    float g0 = cg[mi][ni][half * 2 + 0], g1 = cg[mi][ni][half * 2 + 1];
                    float u0 = cu[mi][ni][half * 2 + 0], u1 = cu[mi][ni][half * 2 + 1];
                    float h0 = g0 / (1.f + expf(-g0)) * u0;
                    float h1 = g1 / (1.f + expf(-g1)) * u1;
                    dst[ni * 4 + tg] = __floats2half2_rn(h0, h1);
                }
            }
        }
    }
}

// ======================================================================
// GEMM2 (fp16 mma.sync, all-cp.async): y[r, n0:n0+128] = w[r]*(hact[r] @ down^T)
// CTA: 64 rows x 128 cols, 256 threads / 8 warps, BK=32.
// ======================================================================
__global__ __launch_bounds__(256, 3) void gemm2_kernel() {
    int bx = blockIdx.x;
    if (bx >= d_nmt) return;
    int e = d_tile_e[bx], base = d_tile_base[bx], lim = d_tile_lim[bx];
    int n0 = blockIdx.y * 128;

    __shared__ __align__(16) uint32_t As[2][64][20];
    __shared__ __align__(16) uint32_t Bs[2][128][20];

    int tid = threadIdx.x;
    int q = tid >> 2, lq = tid & 3;    // q in 0..63
    const __half* aSrc = d_hacth + (size_t)(base + q) * FI + lq * 8;
    const __half* bSrc0 = d_dwnh + ((size_t)e * HD + n0 + q) * FI + lq * 8;
    const __half* bSrc1 = d_dwnh + ((size_t)e * HD + n0 + q + 64) * FI + lq * 8;

    uint32_t asb[2] = { smem_u32(&As[0][0][0]), smem_u32(&As[1][0][0]) };
    uint32_t bsb[2] = { smem_u32(&Bs[0][0][0]), smem_u32(&Bs[1][0][0]) };
    uint32_t aOff = (q * 20 + lq * 4) * 4;
    uint32_t bOff0 = aOff;
    uint32_t bOff1 = ((q + 64) * 20 + lq * 4) * 4;

    int warp = tid >> 5, lane = tid & 31;
    int wm = warp >> 2, wn = warp & 3;
    int g = lane >> 2, tg = lane & 3;
    int offA = ((lane & 7) + ((lane >> 3) & 1) * 8) * 20 + (lane >> 4) * 4;
    int offB = ((lane & 7) + ((lane >> 4) & 1) * 8) * 20 + ((lane >> 3) & 1) * 4;

    float cc[2][4][4] = {};

    const int NIT = FI / 32;           // 24 stages
    cpa16(asb[0] + aOff, aSrc);
    cpa16(bsb[0] + bOff0, bSrc0);
    cpa16(bsb[0] + bOff1, bSrc1);
    CP_COMMIT();

    int buf = 0;
    for (int it = 0; it < NIT; it++) {
        if (it + 1 < NIT) {
            int ko = (it + 1) * 32;
            int d = buf ^ 1;
            cpa16(asb[d] + aOff, aSrc + ko);
            cpa16(bsb[d] + bOff0, bSrc0 + ko);
            cpa16(bsb[d] + bOff1, bSrc1 + ko);
            CP_COMMIT();
            CP_WAIT1();
        } else {
            CP_WAIT0();
        }
        __syncthreads();
#pragma unroll
        for (int kk = 0; kk < 16; kk += 8) {
            uint32_t af[2][4], bb[8];
            ldsm4(af[0], asb[buf] + 4u * (offA + (wm * 32) * 20 + kk));
            ldsm4(af[1], asb[buf] + 4u * (offA + (wm * 32 + 16) * 20 + kk));
            ldsm4(bb + 0, bsb[buf] + 4u * (offB + (wn * 32) * 20 + kk));
            ldsm4(bb + 4, bsb[buf] + 4u * (offB + (wn * 32 + 16) * 20 + kk));
#pragma unroll
            for (int ni = 0; ni < 4; ni++) {
#pragma unroll
                for (int mi = 0; mi < 2; mi++)
                    mma_f16(cc[mi][ni], af[mi], bb[ni * 2], bb[ni * 2 + 1]);
            }
        }
        __syncthreads();
        buf ^= 1;
    }

#pragma unroll
    for (int mi = 0; mi < 2; mi++) {
#pragma unroll
        for (int half = 0; half < 2; half++) {
            int row = wm * 32 + mi * 16 + g + half * 8;
            if (row < lim) {
                float w = d_row_w[base + row];
                float* dst = d_y + (size_t)(base + row) * HD + n0 + wn * 32;
#pragma unroll
                for (int ni = 0; ni < 4; ni++) {
                    float v0 = cc[mi][ni][half * 2 + 0] * w;
                    float v1 = cc[mi][ni][half * 2 + 1] * w;
                    *(float2*)(dst + ni * 8 + tg * 2) = make_float2(v0, v1);
                }
            }
        }
    }
}

// ---------------- deterministic combine ----------------
__global__ void combine_kernel(float* __restrict__ out) {
    int t = blockIdx.x;
    __shared__ int rows[KTOP];
    if (threadIdx.x < KTOP) rows[threadIdx.x] = d_row_of[t * KTOP + threadIdx.x];
    __syncthreads();
    for (int h = threadIdx.x; h < HD; h += blockDim.x) {
        float s = 0.f;
#pragma unroll
        for (int k = 0; k < KTOP; k++) s += d_y[(size_t)rows[k] * HD + h];
        out[(size_t)t * HD + h] = s;
    }
}

// ---------------- launch ----------------
extern "C" void kernel_launch(void* const* d_in, const int* in_sizes, int n_in,
                              void* d_out, int out_size) {
    const float* x   = (const float*)d_in[0];   // [1, 2048, 2048]
    const float* gw  = (const float*)d_in[1];   // [64, 2048]
    const float* gup = (const float*)d_in[2];   // [64, 1536, 2048]
    const float* dwn = (const float*)d_in[3];   // [64, 2048, 768]
    const float* sim = (const float*)d_in[4];   // [64, 64]
    float* out = (float*)d_out;

    const int NCHUNK = (NE * TWOF * HD + NE * HD * FI + T_TOK * HD) / 8;   // 38273024
    router_kernel<<<T_TOK / 4, 256>>>(x, gw);              // launch 0
    cvtwx_kernel<<<NCHUNK / 256, 256>>>(gup, dwn, x);      // launch 1
    routeplan_kernel<<<1, 1024>>>(sim);                    // launch 2
    gemm1_kernel<<<dim3(MAXMT, FI / 64), 128>>>();         // launch 3 (ncu target)
    gemm2_kernel<<<dim3(MAXMT, HD / 128), 256>>>();        // launch 4
    combine_kernel<<<T_TOK, 256>>>(out);                   // launch 5
}

// round 14
// speedup vs baseline: 1.0012x; 1.0012x over previous
#include <cuda_runtime.h>
#include <cuda_fp16.h>
#include <math.h>
#include <stdint.h>

#define T_TOK 2048
#define NE 64
#define KTOP 8
#define SELK 4
#define HD 2048
#define FI 768
#define TWOF 1536
#define BM 64
#define MAXMT 320            // sum ceil(cnt/64) <= 16384/64 + 64
#define CAP 20480            // 16384 + 64*64 padded rows

// ---------------- scratch (device globals; no runtime allocation) ----------------
__device__ float d_topv[T_TOK * KTOP];
__device__ int   d_topi[T_TOK * KTOP];
__device__ int   d_rer[T_TOK * KTOP];
__device__ int d_tile_e[MAXMT];
__device__ int d_tile_base[MAXMT];
__device__ int d_tile_lim[MAXMT];
__device__ int d_nmt;
__device__ int d_row_src[CAP];
__device__ float d_row_w[CAP];
__device__ int d_row_of[T_TOK * KTOP];
__device__ __align__(16) __half d_xh[(size_t)T_TOK * HD];          // fp16 tokens
__device__ __align__(16) __half d_guph[(size_t)NE * TWOF * HD];    // fp16 gate_up (402 MB)
__device__ __align__(16) __half d_dwnh[(size_t)NE * HD * FI];      // fp16 down (201 MB)
__device__ __align__(16) __half d_hacth[(size_t)CAP * FI];         // fp16 silu(g)*u
__device__ float d_y[(size_t)CAP * HD];

// ---------------- helpers (legacy mma.sync path; tcgen05 unavailable:
// harness ptxas target is sm_103 without the 'a' suffix) ----------------------
__device__ __forceinline__ uint32_t packh2(float lo, float hi) {
    uint32_t u;
    asm("cvt.rn.f16x2.f32 %0, %1, %2;" : "=r"(u) : "f"(hi), "f"(lo));
    return u;
}
__device__ __forceinline__ uint2 cvt4h(float4 v) {
    return make_uint2(packh2(v.x, v.y), packh2(v.z, v.w));
}
__device__ __forceinline__ void mma_f16(float* c, const uint32_t* a, uint32_t b0, uint32_t b1) {
    asm volatile(
        "mma.sync.aligned.m16n8k16.row.col.f32.f16.f16.f32 "
        "{%0,%1,%2,%3}, {%4,%5,%6,%7}, {%8,%9}, {%0,%1,%2,%3};\n"
        : "+f"(c[0]), "+f"(c[1]), "+f"(c[2]), "+f"(c[3])
        : "r"(a[0]), "r"(a[1]), "r"(a[2]), "r"(a[3]), "r"(b0), "r"(b1));
}
__device__ __forceinline__ void ldsm4(uint32_t* r, uint32_t a) {
    asm volatile("ldmatrix.sync.aligned.m8n8.x4.shared.b16 {%0,%1,%2,%3}, [%4];"
                 : "=r"(r[0]), "=r"(r[1]), "=r"(r[2]), "=r"(r[3]) : "r"(a));
}
__device__ __forceinline__ uint32_t smem_u32(const void* p) {
    uint32_t a;
    asm("{ .reg .u64 t; cvta.to.shared.u64 t, %1; cvt.u32.u64 %0, t; }" : "=r"(a) : "l"(p));
    return a;
}
__device__ __forceinline__ void cpa16(uint32_t dst, const void* src) {
    asm volatile("cp.async.cg.shared.global [%0], [%1], 16;" :: "r"(dst), "l"(src));
}
#define CP_COMMIT() asm volatile("cp.async.commit_group;" ::: "memory")
#define CP_WAIT1()  asm volatile("cp.async.wait_group 1;" ::: "memory")
#define CP_WAIT0()  asm volatile("cp.async.wait_group 0;" ::: "memory")

// ---------------- router: 4 tokens per block ----------------
__global__ __launch_bounds__(256) void router_kernel(const float* __restrict__ x,
                                                     const float* __restrict__ gw) {
    __shared__ float sx[4][HD];
    __shared__ float sl[4][NE];
    int t0 = blockIdx.x * 4;
    int tid = threadIdx.x;
    for (int i = tid; i < 4 * HD; i += 256)
        ((float*)sx)[i] = x[(size_t)t0 * HD + i];
    __syncthreads();

    int e   = tid >> 2;
    int sub = tid & 3;
    const float4* wp = (const float4*)(gw + (size_t)e * HD + sub * (HD / 4));
    float s0 = 0.f, s1 = 0.f, s2 = 0.f, s3 = 0.f;
    const float4* xp0 = (const float4*)(sx[0] + sub * (HD / 4));
    const float4* xp1 = (const float4*)(sx[1] + sub * (HD / 4));
    const float4* xp2 = (const float4*)(sx[2] + sub * (HD / 4));
    const float4* xp3 = (const float4*)(sx[3] + sub * (HD / 4));
#pragma unroll 4
    for (int i = 0; i < HD / 16; i++) {
        float4 w = wp[i];
        float4 a0 = xp0[i], a1 = xp1[i], a2 = xp2[i], a3 = xp3[i];
        s0 += a0.x * w.x + a0.y * w.y + a0.z * w.z + a0.w * w.w;
        s1 += a1.x * w.x + a1.y * w.y + a1.z * w.z + a1.w * w.w;
        s2 += a2.x * w.x + a2.y * w.y + a2.z * w.z + a2.w * w.w;
        s3 += a3.x * w.x + a3.y * w.y + a3.z * w.z + a3.w * w.w;
    }
    s0 += __shfl_xor_sync(0xffffffffu, s0, 1); s0 += __shfl_xor_sync(0xffffffffu, s0, 2);
    s1 += __shfl_xor_sync(0xffffffffu, s1, 1); s1 += __shfl_xor_sync(0xffffffffu, s1, 2);
    s2 += __shfl_xor_sync(0xffffffffu, s2, 1); s2 += __shfl_xor_sync(0xffffffffu, s2, 2);
    s3 += __shfl_xor_sync(0xffffffffu, s3, 1); s3 += __shfl_xor_sync(0xffffffffu, s3, 2);
    if (sub == 0) { sl[0][e] = s0; sl[1][e] = s1; sl[2][e] = s2; sl[3][e] = s3; }
    __syncthreads();

    int wrp = tid >> 5;
    if (wrp < 4) {
        int lane = tid & 31;
        int t = t0 + wrp;
        float v0 = sl[wrp][lane], v1 = sl[wrp][lane + 32];
        float m = fmaxf(v0, v1);
        for (int off = 16; off; off >>= 1) m = fmaxf(m, __shfl_xor_sync(0xffffffffu, m, off));
        float e0 = expf(v0 - m), e1 = expf(v1 - m);
        float ss = e0 + e1;
        for (int off = 16; off; off >>= 1) ss += __shfl_xor_sync(0xffffffffu, ss, off);
        float p0 = e0 / ss, p1 = e1 / ss;

        float tv[KTOP]; int ti[KTOP];
#pragma unroll
        for (int k = 0; k < KTOP; k++) {
            float b; int bi;
            if (p0 >= p1) { b = p0; bi = lane; } else { b = p1; bi = lane + 32; }
            for (int off = 16; off; off >>= 1) {
                float ob = __shfl_xor_sync(0xffffffffu, b, off);
                int obi  = __shfl_xor_sync(0xffffffffu, bi, off);
                if (ob > b || (ob == b && obi < bi)) { b = ob; bi = obi; }
            }
            tv[k] = b; ti[k] = bi;
            if (bi < 32) { if (lane == bi) p0 = -1.f; }
            else         { if (lane == bi - 32) p1 = -1.f; }
        }
        if (lane == 0) {
            float tsum = 0.f;
#pragma unroll
            for (int k = 0; k < KTOP; k++) tsum += tv[k];
            tsum = fmaxf(tsum, 1e-12f);
#pragma unroll
            for (int k = 0; k < KTOP; k++) {
                d_topv[t * KTOP + k] = tv[k] / tsum;
                d_topi[t * KTOP + k] = ti[k];
            }
        }
    }
}

// ---------------- one-shot fp32 -> fp16 conversion of gup, dwn, x ----------------
__global__ __launch_bounds__(256) void cvtwx_kernel(const float* __restrict__ gup,
                                                    const float* __restrict__ dwn,
                                                    const float* __restrict__ x) {
    const size_t NG = (size_t)NE * TWOF * HD / 8;   // 8-float chunks
    const size_t ND = (size_t)NE * HD * FI / 8;
    const size_t NX = (size_t)T_TOK * HD / 8;
    size_t i = (size_t)blockIdx.x * 256 + threadIdx.x;
    const float4* src; uint4* dst; size_t j;
    if (i < NG)            { src = (const float4*)gup; dst = (uint4*)d_guph; j = i; }
    else if (i < NG + ND)  { src = (const float4*)dwn; dst = (uint4*)d_dwnh; j = i - NG; }
    else if (i < NG + ND + NX) { src = (const float4*)x; dst = (uint4*)d_xh; j = i - NG - ND; }
    else return;
    float4 a = src[j * 2], b = src[j * 2 + 1];
    uint2 p = cvt4h(a), q = cvt4h(b);
    dst[j] = make_uint4(p.x, p.y, q.x, q.y);
}

// ---------------- routeplan: masks -> mapping -> reroute -> tiles -> scatter ----
__global__ __launch_bounds__(1024) void routeplan_kernel(const float* __restrict__ sim) {
    __shared__ unsigned pm[2], smk[2];
    __shared__ int cnts[NE], maps[NE], poff[NE], cur[NE];
    int tid = threadIdx.x;
    if (tid < 2) { pm[tid] = 0u; smk[tid] = 0u; }
    if (tid < NE) { cnts[tid] = 0; cur[tid] = 0; }
    __syncthreads();

    for (int a = tid; a < T_TOK * KTOP; a += 1024) {
        int e0 = d_topi[a];
        if ((a & 7) < SELK) atomicOr(&pm[e0 >> 5], 1u << (e0 & 31));
        else                atomicOr(&smk[e0 >> 5], 1u << (e0 & 31));
    }
    __syncthreads();

    if (tid < NE) {
        int e = tid;
        unsigned pm0 = pm[0], pm1 = pm[1];
        bool prim = (e < 32) ? ((pm0 >> e) & 1) : ((pm1 >> (e - 32)) & 1);
        bool sec  = (e < 32) ? ((smk[0] >> e) & 1) : ((smk[1] >> (e - 32)) & 1);
        int best = 0; float bs = -INFINITY;
        for (int p = 0; p < NE; p++) {
            bool pp = (p < 32) ? ((pm0 >> p) & 1) : ((pm1 >> (p - 32)) & 1);
            if (!pp) continue;
            float v = (p == e) ? 1.0f : sim[e * NE + p];
            if (v > bs) { bs = v; best = p; }
        }
        int mp = e;
        if (sec && !prim && bs >= 0.5f) mp = best;
        maps[e] = mp;
    }
    __syncthreads();

    for (int a = tid; a < T_TOK * KTOP; a += 1024) {
        int e0 = d_topi[a];
        int e = ((a & 7) < SELK) ? e0 : maps[e0];
        d_rer[a] = e;
        atomicAdd(&cnts[e], 1);
    }
    __syncthreads();

    if (tid == 0) {
        int off = 0, nt = 0;
        for (int e = 0; e < NE; e++) {
            poff[e] = off;
            int c = cnts[e];
            int mt = (c + BM - 1) / BM;
            for (int i = 0; i < mt; i++) {
                d_tile_e[nt] = e;
                d_tile_base[nt] = off + i * BM;
                int lm = c - i * BM; if (lm > BM) lm = BM;
                d_tile_lim[nt] = lm;
                nt++;
            }
            off += mt * BM;
        }
        d_nmt = nt;
    }
    __syncthreads();

    for (int a = tid; a < T_TOK * KTOP; a += 1024) {
        int e = d_rer[a];
        int pos = poff[e] + atomicAdd(&cur[e], 1);
        d_row_src[pos] = a >> 3;
        d_row_w[pos] = d_topv[a];
        d_row_of[a] = pos;
    }
}

// ======================================================================
// GEMM1 (fp16 mma.sync, all-cp.async operands) + fused SwiGLU -> fp16 hact.
// CTA: 64 rows x (64 gate + 64 up cols), 4 warps, BK=32 k-halves/stage.
// Per quad (4 lanes x 16B) = one contiguous 64B row-chunk (coalesced).
// ======================================================================
__global__ __launch_bounds__(128, 4) void gemm1_kernel() {
    int bx = blockIdx.x;
    if (bx >= d_nmt) return;
    int e = d_tile_e[bx], base = d_tile_base[bx], lim = d_tile_lim[bx];
    int n0 = blockIdx.y * 64;          // gate column base in [0, 768)

    __shared__ __align__(16) uint32_t As[2][64][20];    // 64 rows x 16 half2 (+pad)
    __shared__ __align__(16) uint32_t Bs[2][128][20];   // rows 0-63 gate, 64-127 up
    __shared__ int srow[64];

    int tid = threadIdx.x;
    // pad rows point at token 0: garbage values, outputs masked by lim
    if (tid < 64) srow[tid] = (tid < lim) ? d_row_src[base + tid] : 0;
    __syncthreads();

    int q = tid >> 2, lq = tid & 3;    // quad row, 16B chunk within 64B row-chunk
    const __half* aSrc0 = d_xh + (size_t)srow[q] * HD + lq * 8;
    const __half* aSrc1 = d_xh + (size_t)srow[q + 32] * HD + lq * 8;
    const __half* bSrc[4];
#pragma unroll
    for (int i = 0; i < 4; i++) {
        int row = q + i * 32;
        int br = (row < 64) ? (n0 + row) : (FI + n0 + (row - 64));
        bSrc[i] = d_guph + ((size_t)e * TWOF + br) * HD + lq * 8;
    }

    uint32_t asb[2] = { smem_u32(&As[0][0][0]), smem_u32(&As[1][0][0]) };
    uint32_t bsb[2] = { smem_u32(&Bs[0][0][0]), smem_u32(&Bs[1][0][0]) };
    uint32_t aOff0 = (q * 20 + lq * 4) * 4;
    uint32_t aOff1 = ((q + 32) * 20 + lq * 4) * 4;
    uint32_t bOff[4];
#pragma unroll
    for (int i = 0; i < 4; i++) bOff[i] = ((q + i * 32) * 20 + lq * 4) * 4;

    int warp = tid >> 5, lane = tid & 31;
    int wm = warp >> 1, wn = warp & 1;
    int g = lane >> 2, tg = lane & 3;
    int offA = ((lane & 7) + ((lane >> 3) & 1) * 8) * 20 + (lane >> 4) * 4;
    int offB = ((lane & 7) + ((lane >> 4) & 1) * 8) * 20 + ((lane >> 3) & 1) * 4;

    float cg[2][4][4] = {};
    float cu[2][4][4] = {};

    const int NIT = HD / 32;           // 64 stages
    // prologue: stage 0 into buffer 0
    cpa16(asb[0] + aOff0, aSrc0);
    cpa16(asb[0] + aOff1, aSrc1);
#pragma unroll
    for (int i = 0; i < 4; i++) cpa16(bsb[0] + bOff[i], bSrc[i]);
    CP_COMMIT();

    int buf = 0;
    for (int it = 0; it < NIT; it++) {
        if (it + 1 < NIT) {
            int ko = (it + 1) * 32;    // halves
            int d = buf ^ 1;
            cpa16(asb[d] + aOff0, aSrc0 + ko);
            cpa16(asb[d] + aOff1, aSrc1 + ko);
#pragma unroll
            for (int i = 0; i < 4; i++) cpa16(bsb[d] + bOff[i], bSrc[i] + ko);
            CP_COMMIT();
            CP_WAIT1();
        } else {
            CP_WAIT0();
        }
        __syncthreads();
#pragma unroll
        for (int kk = 0; kk < 16; kk += 8) {
            uint32_t af[2][4], bg[8], bu[8];
            ldsm4(af[0], asb[buf] + 4u * (offA + (wm * 32) * 20 + kk));
            ldsm4(af[1], asb[buf] + 4u * (offA + (wm * 32 + 16) * 20 + kk));
            ldsm4(bg + 0, bsb[buf] + 4u * (offB + (wn * 32) * 20 + kk));
            ldsm4(bg + 4, bsb[buf] + 4u * (offB + (wn * 32 + 16) * 20 + kk));
            ldsm4(bu + 0, bsb[buf] + 4u * (offB + (64 + wn * 32) * 20 + kk));
            ldsm4(bu + 4, bsb[buf] + 4u * (offB + (64 + wn * 32 + 16) * 20 + kk));
#pragma unroll
            for (int ni = 0; ni < 4; ni++) {
#pragma unroll
                for (int mi = 0; mi < 2; mi++) {
                    mma_f16(cg[mi][ni], af[mi], bg[ni * 2], bg[ni * 2 + 1]);
                    mma_f16(cu[mi][ni], af[mi], bu[ni * 2], bu[ni * 2 + 1]);
                }
            }
        }
        __syncthreads();               // protect buf before it's refilled
        buf ^= 1;
    }

    // fused SwiGLU epilogue -> fp16 hact
#pragma unroll
    for (int mi = 0; mi < 2; mi++) {
#pragma unroll
        for (int half = 0; half < 2; half++) {
            int row = wm * 32 + mi * 16 + g + half * 8;
            if (row < lim) {
                __half2* dst = (__half2*)(d_hacth + (size_t)(base + row) * FI + n0 + wn * 32);
#pragma unroll
                for (int ni = 0; ni < 4; ni++) {
                    float g0 = cg[mi][ni][half * 2 + 0], g1 = cg[mi][ni][half * 2 + 1];
                    float u0 = cu[mi][ni][half * 2 + 0], u1 = cu[mi][ni][half * 2 + 1];
                    float h0 = g0 / (1.f + expf(-g0)) * u0;
                    float h1 = g1 / (1.f + expf(-g1)) * u1;
                    dst[ni * 4 + tg] = __floats2half2_rn(h0, h1);
                }
            }
        }
    }
}

// ======================================================================
// GEMM2 (fp16 mma.sync, all-cp.async): y[r, n0:n0+128] = w[r]*(hact[r] @ down^T)
// CTA: 64 rows x 128 cols, 256 threads / 8 warps, BK=32.
// ======================================================================
__global__ __launch_bounds__(256, 3) void gemm2_kernel() {
    int bx = blockIdx.x;
    if (bx >= d_nmt) return;
    int e = d_tile_e[bx], base = d_tile_base[bx], lim = d_tile_lim[bx];
    int n0 = blockIdx.y * 128;

    __shared__ __align__(16) uint32_t As[2][64][20];
    __shared__ __align__(16) uint32_t Bs[2][128][20];

    int tid = threadIdx.x;
    int q = tid >> 2, lq = tid & 3;    // q in 0..63
    const __half* aSrc = d_hacth + (size_t)(base + q) * FI + lq * 8;
    const __half* bSrc0 = d_dwnh + ((size_t)e * HD + n0 + q) * FI + lq * 8;
    const __half* bSrc1 = d_dwnh + ((size_t)e * HD + n0 + q + 64) * FI + lq * 8;

    uint32_t asb[2] = { smem_u32(&As[0][0][0]), smem_u32(&As[1][0][0]) };
    uint32_t bsb[2] = { smem_u32(&Bs[0][0][0]), smem_u32(&Bs[1][0][0]) };
    uint32_t aOff = (q * 20 + lq * 4) * 4;
    uint32_t bOff0 = aOff;
    uint32_t bOff1 = ((q + 64) * 20 + lq * 4) * 4;

    int warp = tid >> 5, lane = tid & 31;
    int wm = warp >> 2, wn = warp & 3;
    int g = lane >> 2, tg = lane & 3;
    int offA = ((lane & 7) + ((lane >> 3) & 1) * 8) * 20 + (lane >> 4) * 4;
    int offB = ((lane & 7) + ((lane >> 4) & 1) * 8) * 20 + ((lane >> 3) & 1) * 4;

    float cc[2][4][4] = {};

    const int NIT = FI / 32;           // 24 stages
    cpa16(asb[0] + aOff, aSrc);
    cpa16(bsb[0] + bOff0, bSrc0);
    cpa16(bsb[0] + bOff1, bSrc1);
    CP_COMMIT();

    int buf = 0;
    for (int it = 0; it < NIT; it++) {
        if (it + 1 < NIT) {
            int ko = (it + 1) * 32;
            int d = buf ^ 1;
            cpa16(asb[d] + aOff, aSrc + ko);
            cpa16(bsb[d] + bOff0, bSrc0 + ko);
            cpa16(bsb[d] + bOff1, bSrc1 + ko);
            CP_COMMIT();
            CP_WAIT1();
        } else {
            CP_WAIT0();
        }
        __syncthreads();
#pragma unroll
        for (int kk = 0; kk < 16; kk += 8) {
            uint32_t af[2][4], bb[8];
            ldsm4(af[0], asb[buf] + 4u * (offA + (wm * 32) * 20 + kk));
            ldsm4(af[1], asb[buf] + 4u * (offA + (wm * 32 + 16) * 20 + kk));
            ldsm4(bb + 0, bsb[buf] + 4u * (offB + (wn * 32) * 20 + kk));
            ldsm4(bb + 4, bsb[buf] + 4u * (offB + (wn * 32 + 16) * 20 + kk));
#pragma unroll
            for (int ni = 0; ni < 4; ni++) {
#pragma unroll
                for (int mi = 0; mi < 2; mi++)
                    mma_f16(cc[mi][ni], af[mi], bb[ni * 2], bb[ni * 2 + 1]);
            }
        }
        __syncthreads();
        buf ^= 1;
    }

#pragma unroll
    for (int mi = 0; mi < 2; mi++) {
#pragma unroll
        for (int half = 0; half < 2; half++) {
            int row = wm * 32 + mi * 16 + g + half * 8;
            if (row < lim) {
                float w = d_row_w[base + row];
                float* dst = d_y + (size_t)(base + row) * HD + n0 + wn * 32;
#pragma unroll
                for (int ni = 0; ni < 4; ni++) {
                    float v0 = cc[mi][ni][half * 2 + 0] * w;
                    float v1 = cc[mi][ni][half * 2 + 1] * w;
                    *(float2*)(dst + ni * 8 + tg * 2) = make_float2(v0, v1);
                }
            }
        }
    }
}

// ---------------- deterministic combine ----------------
__global__ void combine_kernel(float* __restrict__ out) {
    int t = blockIdx.x;
    __shared__ int rows[KTOP];
    if (threadIdx.x < KTOP) rows[threadIdx.x] = d_row_of[t * KTOP + threadIdx.x];
    __syncthreads();
    for (int h = threadIdx.x; h < HD; h += blockDim.x) {
        float s = 0.f;
#pragma unroll
        for (int k = 0; k < KTOP; k++) s += d_y[(size_t)rows[k] * HD + h];
        out[(size_t)t * HD + h] = s;
    }
}

// ---------------- launch ----------------
extern "C" void kernel_launch(void* const* d_in, const int* in_sizes, int n_in,
                              void* d_out, int out_size) {
    const float* x   = (const float*)d_in[0];   // [1, 2048, 2048]
    const float* gw  = (const float*)d_in[1];   // [64, 2048]
    const float* gup = (const float*)d_in[2];   // [64, 1536, 2048]
    const float* dwn = (const float*)d_in[3];   // [64, 2048, 768]
    const float* sim = (const float*)d_in[4];   // [64, 64]
    float* out = (float*)d_out;

    const int NCHUNK = (NE * TWOF * HD + NE * HD * FI + T_TOK * HD) / 8;   // 38273024
    router_kernel<<<T_TOK / 4, 256>>>(x, gw);              // launch 0
    cvtwx_kernel<<<NCHUNK / 256, 256>>>(gup, dwn, x);      // launch 1
    routeplan_kernel<<<1, 1024>>>(sim);                    // launch 2
    gemm1_kernel<<<dim3(MAXMT, FI / 64), 128>>>();         // launch 3 (ncu target)
    gemm2_kernel<<<dim3(MAXMT, HD / 128), 256>>>();        // launch 4
    combine_kernel<<<T_TOK, 256>>>(out);                   // launch 5
}

// round 15
// speedup vs baseline: 1.0579x; 1.0566x over previous
#include <cuda_runtime.h>
#include <cuda_fp16.h>
#include <math.h>
#include <stdint.h>

#define T_TOK 2048
#define NE 64
#define KTOP 8
#define SELK 4
#define HD 2048
#define FI 768
#define TWOF 1536
#define BM 64
#define MAXMT 320            // sum ceil(cnt/64) <= 16384/64 + 64
#define CAP 20480            // 16384 + 64*64 padded rows

// ---------------- scratch (device globals; no runtime allocation) ----------------
__device__ float d_topv[T_TOK * KTOP];
__device__ int   d_topi[T_TOK * KTOP];
__device__ int   d_rer[T_TOK * KTOP];
__device__ int d_tile_e[MAXMT];
__device__ int d_tile_base[MAXMT];
__device__ int d_tile_lim[MAXMT];
__device__ int d_nmt;
__device__ int d_row_src[CAP];
__device__ float d_row_w[CAP];
__device__ int d_row_of[T_TOK * KTOP];
__device__ __align__(16) __half d_xh[(size_t)T_TOK * HD];          // fp16 tokens
__device__ __align__(16) __half d_guph[(size_t)NE * TWOF * HD];    // fp16 gate_up (402 MB)
__device__ __align__(16) __half d_dwnh[(size_t)NE * HD * FI];      // fp16 down (201 MB)
__device__ __align__(16) __half d_hacth[(size_t)CAP * FI];         // fp16 silu(g)*u
__device__ float d_y[(size_t)CAP * HD];

// ---------------- helpers (legacy mma.sync path; tcgen05 unavailable:
// harness ptxas target is sm_103 without the 'a' suffix) ----------------------
__device__ __forceinline__ uint32_t packh2(float lo, float hi) {
    uint32_t u;
    asm("cvt.rn.f16x2.f32 %0, %1, %2;" : "=r"(u) : "f"(hi), "f"(lo));
    return u;
}
__device__ __forceinline__ uint2 cvt4h(float4 v) {
    return make_uint2(packh2(v.x, v.y), packh2(v.z, v.w));
}
__device__ __forceinline__ void mma_f16(float* c, const uint32_t* a, uint32_t b0, uint32_t b1) {
    asm volatile(
        "mma.sync.aligned.m16n8k16.row.col.f32.f16.f16.f32 "
        "{%0,%1,%2,%3}, {%4,%5,%6,%7}, {%8,%9}, {%0,%1,%2,%3};\n"
        : "+f"(c[0]), "+f"(c[1]), "+f"(c[2]), "+f"(c[3])
        : "r"(a[0]), "r"(a[1]), "r"(a[2]), "r"(a[3]), "r"(b0), "r"(b1));
}
__device__ __forceinline__ void ldsm4(uint32_t* r, uint32_t a) {
    asm volatile("ldmatrix.sync.aligned.m8n8.x4.shared.b16 {%0,%1,%2,%3}, [%4];"
                 : "=r"(r[0]), "=r"(r[1]), "=r"(r[2]), "=r"(r[3]) : "r"(a));
}
__device__ __forceinline__ uint32_t smem_u32(const void* p) {
    uint32_t a;
    asm("{ .reg .u64 t; cvta.to.shared.u64 t, %1; cvt.u32.u64 %0, t; }" : "=r"(a) : "l"(p));
    return a;
}
__device__ __forceinline__ void cpa16(uint32_t dst, const void* src) {
    asm volatile("cp.async.cg.shared.global [%0], [%1], 16;" :: "r"(dst), "l"(src));
}
#define CP_COMMIT() asm volatile("cp.async.commit_group;" ::: "memory")
#define CP_WAIT1()  asm volatile("cp.async.wait_group 1;" ::: "memory")

// ---------------- router: 4 tokens per block ----------------
__global__ __launch_bounds__(256) void router_kernel(const float* __restrict__ x,
                                                     const float* __restrict__ gw) {
    __shared__ float sx[4][HD];
    __shared__ float sl[4][NE];
    int t0 = blockIdx.x * 4;
    int tid = threadIdx.x;
    for (int i = tid; i < 4 * HD; i += 256)
        ((float*)sx)[i] = x[(size_t)t0 * HD + i];
    __syncthreads();

    int e   = tid >> 2;
    int sub = tid & 3;
    const float4* wp = (const float4*)(gw + (size_t)e * HD + sub * (HD / 4));
    float s0 = 0.f, s1 = 0.f, s2 = 0.f, s3 = 0.f;
    const float4* xp0 = (const float4*)(sx[0] + sub * (HD / 4));
    const float4* xp1 = (const float4*)(sx[1] + sub * (HD / 4));
    const float4* xp2 = (const float4*)(sx[2] + sub * (HD / 4));
    const float4* xp3 = (const float4*)(sx[3] + sub * (HD / 4));
#pragma unroll 4
    for (int i = 0; i < HD / 16; i++) {
        float4 w = wp[i];
        float4 a0 = xp0[i], a1 = xp1[i], a2 = xp2[i], a3 = xp3[i];
        s0 += a0.x * w.x + a0.y * w.y + a0.z * w.z + a0.w * w.w;
        s1 += a1.x * w.x + a1.y * w.y + a1.z * w.z + a1.w * w.w;
        s2 += a2.x * w.x + a2.y * w.y + a2.z * w.z + a2.w * w.w;
        s3 += a3.x * w.x + a3.y * w.y + a3.z * w.z + a3.w * w.w;
    }
    s0 += __shfl_xor_sync(0xffffffffu, s0, 1); s0 += __shfl_xor_sync(0xffffffffu, s0, 2);
    s1 += __shfl_xor_sync(0xffffffffu, s1, 1); s1 += __shfl_xor_sync(0xffffffffu, s1, 2);
    s2 += __shfl_xor_sync(0xffffffffu, s2, 1); s2 += __shfl_xor_sync(0xffffffffu, s2, 2);
    s3 += __shfl_xor_sync(0xffffffffu, s3, 1); s3 += __shfl_xor_sync(0xffffffffu, s3, 2);
    if (sub == 0) { sl[0][e] = s0; sl[1][e] = s1; sl[2][e] = s2; sl[3][e] = s3; }
    __syncthreads();

    int wrp = tid >> 5;
    if (wrp < 4) {
        int lane = tid & 31;
        int t = t0 + wrp;
        float v0 = sl[wrp][lane], v1 = sl[wrp][lane + 32];
        float m = fmaxf(v0, v1);
        for (int off = 16; off; off >>= 1) m = fmaxf(m, __shfl_xor_sync(0xffffffffu, m, off));
        float e0 = expf(v0 - m), e1 = expf(v1 - m);
        float ss = e0 + e1;
        for (int off = 16; off; off >>= 1) ss += __shfl_xor_sync(0xffffffffu, ss, off);
        float p0 = e0 / ss, p1 = e1 / ss;

        float tv[KTOP]; int ti[KTOP];
#pragma unroll
        for (int k = 0; k < KTOP; k++) {
            float b; int bi;
            if (p0 >= p1) { b = p0; bi = lane; } else { b = p1; bi = lane + 32; }
            for (int off = 16; off; off >>= 1) {
                float ob = __shfl_xor_sync(0xffffffffu, b, off);
                int obi  = __shfl_xor_sync(0xffffffffu, bi, off);
                if (ob > b || (ob == b && obi < bi)) { b = ob; bi = obi; }
            }
            tv[k] = b; ti[k] = bi;
            if (bi < 32) { if (lane == bi) p0 = -1.f; }
            else         { if (lane == bi - 32) p1 = -1.f; }
        }
        if (lane == 0) {
            float tsum = 0.f;
#pragma unroll
            for (int k = 0; k < KTOP; k++) tsum += tv[k];
            tsum = fmaxf(tsum, 1e-12f);
#pragma unroll
            for (int k = 0; k < KTOP; k++) {
                d_topv[t * KTOP + k] = tv[k] / tsum;
                d_topi[t * KTOP + k] = ti[k];
            }
        }
    }
}

// ---------------- one-shot fp32 -> fp16 conversion of gup, dwn, x ----------------
__global__ __launch_bounds__(256) void cvtwx_kernel(const float* __restrict__ gup,
                                                    const float* __restrict__ dwn,
                                                    const float* __restrict__ x) {
    const size_t NG = (size_t)NE * TWOF * HD / 8;   // 8-float chunks
    const size_t ND = (size_t)NE * HD * FI / 8;
    const size_t NX = (size_t)T_TOK * HD / 8;
    size_t i = (size_t)blockIdx.x * 256 + threadIdx.x;
    const float4* src; uint4* dst; size_t j;
    if (i < NG)            { src = (const float4*)gup; dst = (uint4*)d_guph; j = i; }
    else if (i < NG + ND)  { src = (const float4*)dwn; dst = (uint4*)d_dwnh; j = i - NG; }
    else if (i < NG + ND + NX) { src = (const float4*)x; dst = (uint4*)d_xh; j = i - NG - ND; }
    else return;
    float4 a = src[j * 2], b = src[j * 2 + 1];
    uint2 p = cvt4h(a), q = cvt4h(b);
    dst[j] = make_uint4(p.x, p.y, q.x, q.y);
}

// ---------------- routeplan: masks -> mapping -> reroute -> tiles -> scatter ----
__global__ __launch_bounds__(1024) void routeplan_kernel(const float* __restrict__ sim) {
    __shared__ unsigned pm[2], smk[2];
    __shared__ int cnts[NE], maps[NE], poff[NE], cur[NE];
    int tid = threadIdx.x;
    if (tid < 2) { pm[tid] = 0u; smk[tid] = 0u; }
    if (tid < NE) { cnts[tid] = 0; cur[tid] = 0; }
    __syncthreads();

    for (int a = tid; a < T_TOK * KTOP; a += 1024) {
        int e0 = d_topi[a];
        if ((a & 7) < SELK) atomicOr(&pm[e0 >> 5], 1u << (e0 & 31));
        else                atomicOr(&smk[e0 >> 5], 1u << (e0 & 31));
    }
    __syncthreads();

    if (tid < NE) {
        int e = tid;
        unsigned pm0 = pm[0], pm1 = pm[1];
        bool prim = (e < 32) ? ((pm0 >> e) & 1) : ((pm1 >> (e - 32)) & 1);
        bool sec  = (e < 32) ? ((smk[0] >> e) & 1) : ((smk[1] >> (e - 32)) & 1);
        int best = 0; float bs = -INFINITY;
        for (int p = 0; p < NE; p++) {
            bool pp = (p < 32) ? ((pm0 >> p) & 1) : ((pm1 >> (p - 32)) & 1);
            if (!pp) continue;
            float v = (p == e) ? 1.0f : sim[e * NE + p];
            if (v > bs) { bs = v; best = p; }
        }
        int mp = e;
        if (sec && !prim && bs >= 0.5f) mp = best;
        maps[e] = mp;
    }
    __syncthreads();

    for (int a = tid; a < T_TOK * KTOP; a += 1024) {
        int e0 = d_topi[a];
        int e = ((a & 7) < SELK) ? e0 : maps[e0];
        d_rer[a] = e;
        atomicAdd(&cnts[e], 1);
    }
    __syncthreads();

    if (tid == 0) {
        int off = 0, nt = 0;
        for (int e = 0; e < NE; e++) {
            poff[e] = off;
            int c = cnts[e];
            int mt = (c + BM - 1) / BM;
            for (int i = 0; i < mt; i++) {
                d_tile_e[nt] = e;
                d_tile_base[nt] = off + i * BM;
                int lm = c - i * BM; if (lm > BM) lm = BM;
                d_tile_lim[nt] = lm;
                nt++;
            }
            off += mt * BM;
        }
        d_nmt = nt;
    }
    __syncthreads();

    for (int a = tid; a < T_TOK * KTOP; a += 1024) {
        int e = d_rer[a];
        int pos = poff[e] + atomicAdd(&cur[e], 1);
        d_row_src[pos] = a >> 3;
        d_row_w[pos] = d_topv[a];
        d_row_of[a] = pos;
    }
}

// ======================================================================
// GEMM1 (fp16 mma.sync, cp.async 3-stage ring, ONE sync per stage)
// + fused SwiGLU -> fp16 hact. CTA: 64 rows x (64 gate + 64 up), 4 warps.
// ======================================================================
#define A1_STG 5120              // 64*20*4 bytes per stage
#define B1_STG 10240             // 128*20*4 bytes per stage
__global__ __launch_bounds__(128, 4) void gemm1_kernel() {
    int bx = blockIdx.x;
    if (bx >= d_nmt) return;
    int e = d_tile_e[bx], base = d_tile_base[bx], lim = d_tile_lim[bx];
    int n0 = blockIdx.y * 64;          // gate column base in [0, 768)

    __shared__ __align__(16) uint32_t As[3][64][20];
    __shared__ __align__(16) uint32_t Bs[3][128][20];
    __shared__ int srow[64];

    int tid = threadIdx.x;
    if (tid < 64) srow[tid] = (tid < lim) ? d_row_src[base + tid] : 0;
    __syncthreads();

    int q = tid >> 2, lq = tid & 3;    // quad row, 16B chunk within 64B row-chunk
    const __half* aSrc0 = d_xh + (size_t)srow[q] * HD + lq * 8;
    const __half* aSrc1 = d_xh + (size_t)srow[q + 32] * HD + lq * 8;
    const __half* bSrc[4];
#pragma unroll
    for (int i = 0; i < 4; i++) {
        int row = q + i * 32;
        int br = (row < 64) ? (n0 + row) : (FI + n0 + (row - 64));
        bSrc[i] = d_guph + ((size_t)e * TWOF + br) * HD + lq * 8;
    }

    uint32_t asb0 = smem_u32(&As[0][0][0]);
    uint32_t bsb0 = smem_u32(&Bs[0][0][0]);
    uint32_t aOff0 = (q * 20 + lq * 4) * 4;
    uint32_t aOff1 = ((q + 32) * 20 + lq * 4) * 4;
    uint32_t bOff[4];
#pragma unroll
    for (int i = 0; i < 4; i++) bOff[i] = ((q + i * 32) * 20 + lq * 4) * 4;

    int warp = tid >> 5, lane = tid & 31;
    int wm = warp >> 1, wn = warp & 1;
    int g = lane >> 2, tg = lane & 3;
    int offA = ((lane & 7) + ((lane >> 3) & 1) * 8) * 20 + (lane >> 4) * 4;
    int offB = ((lane & 7) + ((lane >> 4) & 1) * 8) * 20 + ((lane >> 3) & 1) * 4;

    float cg[2][4][4] = {};
    float cu[2][4][4] = {};

    const int NIT = HD / 32;           // 64 stages
    // prologue: stages 0,1 into buffers 0,1
#pragma unroll
    for (int s = 0; s < 2; s++) {
        uint32_t ab = asb0 + s * A1_STG, bb = bsb0 + s * B1_STG;
        int ko = s * 32;
        cpa16(ab + aOff0, aSrc0 + ko);
        cpa16(ab + aOff1, aSrc1 + ko);
#pragma unroll
        for (int i = 0; i < 4; i++) cpa16(bb + bOff[i], bSrc[i] + ko);
        CP_COMMIT();
    }

    int buf = 0, fbuf = 2;
    for (int it = 0; it < NIT; it++) {
        CP_WAIT1();                    // stage `it` resident
        __syncthreads();               // visible to all; buffer fbuf fully consumed
        if (it + 2 < NIT) {            // issue stage it+2 into fbuf (overlaps compute)
            uint32_t ab = asb0 + fbuf * A1_STG, bb = bsb0 + fbuf * B1_STG;
            int ko = (it + 2) * 32;
            cpa16(ab + aOff0, aSrc0 + ko);
            cpa16(ab + aOff1, aSrc1 + ko);
#pragma unroll
            for (int i = 0; i < 4; i++) cpa16(bb + bOff[i], bSrc[i] + ko);
        }
        CP_COMMIT();                   // commit (possibly empty) keeps wait invariant
        uint32_t ab = asb0 + buf * A1_STG;
        uint32_t bb = bsb0 + buf * B1_STG;
#pragma unroll
        for (int kk = 0; kk < 16; kk += 8) {
            uint32_t af[2][4], bg[8], bu[8];
            ldsm4(af[0], ab + 4u * (offA + (wm * 32) * 20 + kk));
            ldsm4(af[1], ab + 4u * (offA + (wm * 32 + 16) * 20 + kk));
            ldsm4(bg + 0, bb + 4u * (offB + (wn * 32) * 20 + kk));
            ldsm4(bg + 4, bb + 4u * (offB + (wn * 32 + 16) * 20 + kk));
            ldsm4(bu + 0, bb + 4u * (offB + (64 + wn * 32) * 20 + kk));
            ldsm4(bu + 4, bb + 4u * (offB + (64 + wn * 32 + 16) * 20 + kk));
#pragma unroll
            for (int ni = 0; ni < 4; ni++) {
#pragma unroll
                for (int mi = 0; mi < 2; mi++) {
                    mma_f16(cg[mi][ni], af[mi], bg[ni * 2], bg[ni * 2 + 1]);
                    mma_f16(cu[mi][ni], af[mi], bu[ni * 2], bu[ni * 2 + 1]);
                }
            }
        }
        if (++buf == 3) buf = 0;
        if (++fbuf == 3) fbuf = 0;
    }

    // fused SwiGLU epilogue -> fp16 hact
#pragma unroll
    for (int mi = 0; mi < 2; mi++) {
#pragma unroll
        for (int half = 0; half < 2; half++) {
            int row = wm * 32 + mi * 16 + g + half * 8;
            if (row < lim) {
                __half2* dst = (__half2*)(d_hacth + (size_t)(base + row) * FI + n0 + wn * 32);
#pragma unroll
                for (int ni = 0; ni < 4; ni++) {
                    float g0 = cg[mi][ni][half * 2 + 0], g1 = cg[mi][ni][half * 2 + 1];
                    float u0 = cu[mi][ni][half * 2 + 0], u1 = cu[mi][ni][half * 2 + 1];
                    float h0 = g0 / (1.f + expf(-g0)) * u0;
                    float h1 = g1 / (1.f + expf(-g1)) * u1;
                    dst[ni * 4 + tg] = __floats2half2_rn(h0, h1);
                }
            }
        }
    }
}

// ======================================================================
// GEMM2 (fp16 mma.sync, cp.async 3-stage ring): y = w * (hact @ down^T)
// CTA: 64 rows x 128 cols, 256 threads / 8 warps.
// ======================================================================
#define A2_STG 5120
#define B2_STG 10240
__global__ __launch_bounds__(256, 3) void gemm2_kernel() {
    int bx = blockIdx.x;
    if (bx >= d_nmt) return;
    int e = d_tile_e[bx], base = d_tile_base[bx], lim = d_tile_lim[bx];
    int n0 = blockIdx.y * 128;

    __shared__ __align__(16) uint32_t As[3][64][20];
    __shared__ __align__(16) uint32_t Bs[3][128][20];

    int tid = threadIdx.x;
    int q = tid >> 2, lq = tid & 3;    // q in 0..63
    const __half* aSrc = d_hacth + (size_t)(base + q) * FI + lq * 8;
    const __half* bSrc0 = d_dwnh + ((size_t)e * HD + n0 + q) * FI + lq * 8;
    const __half* bSrc1 = d_dwnh + ((size_t)e * HD + n0 + q + 64) * FI + lq * 8;

    uint32_t asb0 = smem_u32(&As[0][0][0]);
    uint32_t bsb0 = smem_u32(&Bs[0][0][0]);
    uint32_t aOff = (q * 20 + lq * 4) * 4;
    uint32_t bOff0 = aOff;
    uint32_t bOff1 = ((q + 64) * 20 + lq * 4) * 4;

    int warp = tid >> 5, lane = tid & 31;
    int wm = warp >> 2, wn = warp & 3;
    int g = lane >> 2, tg = lane & 3;
    int offA = ((lane & 7) + ((lane >> 3) & 1) * 8) * 20 + (lane >> 4) * 4;
    int offB = ((lane & 7) + ((lane >> 4) & 1) * 8) * 20 + ((lane >> 3) & 1) * 4;

    float cc[2][4][4] = {};

    const int NIT = FI / 32;           // 24 stages
#pragma unroll
    for (int s = 0; s < 2; s++) {
        uint32_t ab = asb0 + s * A2_STG, bb = bsb0 + s * B2_STG;
        int ko = s * 32;
        cpa16(ab + aOff, aSrc + ko);
        cpa16(bb + bOff0, bSrc0 + ko);
        cpa16(bb + bOff1, bSrc1 + ko);
        CP_COMMIT();
    }

    int buf = 0, fbuf = 2;
    for (int it = 0; it < NIT; it++) {
        CP_WAIT1();
        __syncthreads();
        if (it + 2 < NIT) {
            uint32_t ab = asb0 + fbuf * A2_STG, bb = bsb0 + fbuf * B2_STG;
            int ko = (it + 2) * 32;
            cpa16(ab + aOff, aSrc + ko);
            cpa16(bb + bOff0, bSrc0 + ko);
            cpa16(bb + bOff1, bSrc1 + ko);
        }
        CP_COMMIT();
        uint32_t ab = asb0 + buf * A2_STG;
        uint32_t bb = bsb0 + buf * B2_STG;
#pragma unroll
        for (int kk = 0; kk < 16; kk += 8) {
            uint32_t af[2][4], bb4[8];
            ldsm4(af[0], ab + 4u * (offA + (wm * 32) * 20 + kk));
            ldsm4(af[1], ab + 4u * (offA + (wm * 32 + 16) * 20 + kk));
            ldsm4(bb4 + 0, bb + 4u * (offB + (wn * 32) * 20 + kk));
            ldsm4(bb4 + 4, bb + 4u * (offB + (wn * 32 + 16) * 20 + kk));
#pragma unroll
            for (int ni = 0; ni < 4; ni++) {
#pragma unroll
                for (int mi = 0; mi < 2; mi++)
                    mma_f16(cc[mi][ni], af[mi], bb4[ni * 2], bb4[ni * 2 + 1]);
            }
        }
        if (++buf == 3) buf = 0;
        if (++fbuf == 3) fbuf = 0;
    }

#pragma unroll
    for (int mi = 0; mi < 2; mi++) {
#pragma unroll
        for (int half = 0; half < 2; half++) {
            int row = wm * 32 + mi * 16 + g + half * 8;
            if (row < lim) {
                float w = d_row_w[base + row];
                float* dst = d_y + (size_t)(base + row) * HD + n0 + wn * 32;
#pragma unroll
                for (int ni = 0; ni < 4; ni++) {
                    float v0 = cc[mi][ni][half * 2 + 0] * w;
                    float v1 = cc[mi][ni][half * 2 + 1] * w;
                    *(float2*)(dst + ni * 8 + tg * 2) = make_float2(v0, v1);
                }
            }
        }
    }
}

// ---------------- deterministic combine ----------------
__global__ void combine_kernel(float* __restrict__ out) {
    int t = blockIdx.x;
    __shared__ int rows[KTOP];
    if (threadIdx.x < KTOP) rows[threadIdx.x] = d_row_of[t * KTOP + threadIdx.x];
    __syncthreads();
    for (int h = threadIdx.x; h < HD; h += blockDim.x) {
        float s = 0.f;
#pragma unroll
        for (int k = 0; k < KTOP; k++) s += d_y[(size_t)rows[k] * HD + h];
        out[(size_t)t * HD + h] = s;
    }
}

// ---------------- launch ----------------
extern "C" void kernel_launch(void* const* d_in, const int* in_sizes, int n_in,
                              void* d_out, int out_size) {
    const float* x   = (const float*)d_in[0];   // [1, 2048, 2048]
    const float* gw  = (const float*)d_in[1];   // [64, 2048]
    const float* gup = (const float*)d_in[2];   // [64, 1536, 2048]
    const float* dwn = (const float*)d_in[3];   // [64, 2048, 768]
    const float* sim = (const float*)d_in[4];   // [64, 64]
    float* out = (float*)d_out;

    const int NCHUNK = (NE * TWOF * HD + NE * HD * FI + T_TOK * HD) / 8;   // 38273024
    router_kernel<<<T_TOK / 4, 256>>>(x, gw);              // launch 0
    cvtwx_kernel<<<NCHUNK / 256, 256>>>(gup, dwn, x);      // launch 1
    routeplan_kernel<<<1, 1024>>>(sim);                    // launch 2
    gemm1_kernel<<<dim3(MAXMT, FI / 64), 128>>>();         // launch 3 (ncu target)
    gemm2_kernel<<<dim3(MAXMT, HD / 128), 256>>>();        // launch 4
    combine_kernel<<<T_TOK, 256>>>(out);                   // launch 5
}